// round 9
// baseline (speedup 1.0000x reference)
#include <cuda_runtime.h>

#define DDIM 1024
#define BSZ  16384

// Ping-pong scratch for the D x D polynomial buildup (16 MB total).
__device__ float g_s0[DDIM * DDIM];
__device__ float g_s1[DDIM * DDIM];
__device__ float g_s2[DDIM * DDIM];
__device__ float g_s3[DDIM * DDIM];

// P = I + A ; Bm = A
__global__ void init_PB(const float* __restrict__ A, float* __restrict__ P,
                        float* __restrict__ Bm) {
    int i = blockIdx.x * blockDim.x + threadIdx.x;
    float a = A[i];
    Bm[i] = a;
    int r = i >> 10;           // D = 1024
    int c = i & (DDIM - 1);
    P[i] = a + (r == c ? 1.0f : 0.0f);
}

// C[M,N] = A[M,K] * B[K,N] (+ Cs) (then optional *w + bias epilogue).
// All matrices row-major. M,N,K multiples of BM/BN/BK (no bounds checks).
// k-loop is software-pipelined: tile k+1 is prefetched into registers while
// tile k is consumed from shared memory (single smem buffer, 2 barriers/iter).
template <int BM, int BN, int BK, int TM, int TN, bool EPI>
__global__ void __launch_bounds__((BM / TM) * (BN / TN))
gemm_k(const float* __restrict__ A, const float* __restrict__ Bm,
       const float* __restrict__ Cs, float* __restrict__ C,
       int M, int N, int K,
       const float* __restrict__ w, const float* __restrict__ bias) {
    constexpr int THREADS = (BM / TM) * (BN / TN);
    __shared__ float As[BK][BM];
    __shared__ float Bs[BK][BN];

    const int tid = threadIdx.x;
    const int bm = blockIdx.y, bn = blockIdx.x;
    const int tx = tid % (BN / TN);
    const int ty = tid / (BN / TN);

    // A-tile load mapping: float4 along K
    constexpr int A_TPR = BK / 4;                 // threads per A row
    const int aRow = tid / A_TPR;
    const int aCol = (tid % A_TPR) * 4;
    constexpr int A_RSTRIDE = THREADS / A_TPR;
    constexpr int A_ITERS = BM / A_RSTRIDE;
    // B-tile load mapping: float4 along N
    constexpr int B_TPR = BN / 4;
    const int bRow = tid / B_TPR;
    const int bCol = (tid % B_TPR) * 4;
    constexpr int B_RSTRIDE = THREADS / B_TPR;
    constexpr int B_ITERS = BK / B_RSTRIDE;

    float acc[TM][TN];
#pragma unroll
    for (int i = 0; i < TM; i++)
#pragma unroll
        for (int j = 0; j < TN; j++) acc[i][j] = 0.0f;

    const float* Ab = A + (size_t)bm * BM * K;
    const float* Bb = Bm + (size_t)bn * BN;

    float4 aReg[A_ITERS], bReg[B_ITERS];
    // Prologue: stage tile k0=0 into registers.
#pragma unroll
    for (int r = 0; r < A_ITERS; r++)
        aReg[r] = *(const float4*)(Ab + (size_t)(r * A_RSTRIDE + aRow) * K + aCol);
#pragma unroll
    for (int r = 0; r < B_ITERS; r++)
        bReg[r] = *(const float4*)(Bb + (size_t)(r * B_RSTRIDE + bRow) * N + bCol);

    for (int k0 = 0; k0 < K; k0 += BK) {
        // Commit staged registers to shared memory.
#pragma unroll
        for (int r = 0; r < A_ITERS; r++) {
            As[aCol + 0][r * A_RSTRIDE + aRow] = aReg[r].x;
            As[aCol + 1][r * A_RSTRIDE + aRow] = aReg[r].y;
            As[aCol + 2][r * A_RSTRIDE + aRow] = aReg[r].z;
            As[aCol + 3][r * A_RSTRIDE + aRow] = aReg[r].w;
        }
#pragma unroll
        for (int r = 0; r < B_ITERS; r++)
            *(float4*)(&Bs[r * B_RSTRIDE + bRow][bCol]) = bReg[r];
        __syncthreads();

        // Prefetch tile k0+BK while computing on tile k0.
        if (k0 + BK < K) {
#pragma unroll
            for (int r = 0; r < A_ITERS; r++)
                aReg[r] = *(const float4*)(Ab + (size_t)(r * A_RSTRIDE + aRow) * K + (k0 + BK) + aCol);
#pragma unroll
            for (int r = 0; r < B_ITERS; r++)
                bReg[r] = *(const float4*)(Bb + (size_t)(k0 + BK + r * B_RSTRIDE + bRow) * N + bCol);
        }

#pragma unroll
        for (int kk = 0; kk < BK; kk++) {
            float ar[TM], br[TN];
#pragma unroll
            for (int i = 0; i < TM; i++) ar[i] = As[kk][ty * TM + i];
#pragma unroll
            for (int j = 0; j < TN; j++) br[j] = Bs[kk][tx * TN + j];
#pragma unroll
            for (int i = 0; i < TM; i++)
#pragma unroll
                for (int j = 0; j < TN; j++)
                    acc[i][j] = fmaf(ar[i], br[j], acc[i][j]);
        }
        __syncthreads();
    }

#pragma unroll
    for (int i = 0; i < TM; i++) {
        int gr = bm * BM + ty * TM + i;
#pragma unroll
        for (int j = 0; j < TN; j++) {
            int gc = bn * BN + tx * TN + j;
            float v = acc[i][j];
            if (Cs) v += Cs[(size_t)gr * N + gc];
            if (EPI) v = v * w[gc] + bias[gc];
            C[(size_t)gr * N + gc] = v;
        }
    }
}

extern "C" void kernel_launch(void* const* d_in, const int* in_sizes, int n_in,
                              void* d_out, int out_size) {
    const float* eps = (const float*)d_in[0];
    const float* A   = (const float*)d_in[1];
    const float* w   = (const float*)d_in[2];
    const float* b   = (const float*)d_in[3];
    float* out = (float*)d_out;

    float *g0, *g1, *g2, *g3;
    cudaGetSymbolAddress((void**)&g0, g_s0);
    cudaGetSymbolAddress((void**)&g1, g_s1);
    cudaGetSymbolAddress((void**)&g2, g_s2);
    cudaGetSymbolAddress((void**)&g3, g_s3);

    // P (g0) = I + A, B (g2) = A
    init_PB<<<(DDIM * DDIM) / 256, 256>>>(A, g0, g2);

    dim3 gs(DDIM / 64, DDIM / 64);   // 16x16 = 256 CTAs for small GEMMs
    // (I-A)^{-1} ~= (I+A)(I+A^2)(I+A^4)(I+A^8)(I+A^16)  [Neumann deg 31]
    // j0: B2 = g3 = g2*g2 (A^2); P = g1 = g0 + g0*g3
    gemm_k<64, 64, 16, 4, 4, false><<<gs, 256>>>(g2, g2, nullptr, g3, DDIM, DDIM, DDIM, nullptr, nullptr);
    gemm_k<64, 64, 16, 4, 4, false><<<gs, 256>>>(g0, g3, g0, g1, DDIM, DDIM, DDIM, nullptr, nullptr);
    // j1: B2 = g2 = g3*g3 (A^4); P = g0 = g1 + g1*g2
    gemm_k<64, 64, 16, 4, 4, false><<<gs, 256>>>(g3, g3, nullptr, g2, DDIM, DDIM, DDIM, nullptr, nullptr);
    gemm_k<64, 64, 16, 4, 4, false><<<gs, 256>>>(g1, g2, g1, g0, DDIM, DDIM, DDIM, nullptr, nullptr);
    // j2: B2 = g3 = g2*g2 (A^8); P = g1 = g0 + g0*g3
    gemm_k<64, 64, 16, 4, 4, false><<<gs, 256>>>(g2, g2, nullptr, g3, DDIM, DDIM, DDIM, nullptr, nullptr);
    gemm_k<64, 64, 16, 4, 4, false><<<gs, 256>>>(g0, g3, g0, g1, DDIM, DDIM, DDIM, nullptr, nullptr);
    // j3: B2 = g2 = g3*g3 (A^16); P = g0 = g1 + g1*g2
    gemm_k<64, 64, 16, 4, 4, false><<<gs, 256>>>(g3, g3, nullptr, g2, DDIM, DDIM, DDIM, nullptr, nullptr);
    gemm_k<64, 64, 16, 4, 4, false><<<gs, 256>>>(g1, g2, g1, g0, DDIM, DDIM, DDIM, nullptr, nullptr);

    // out = (eps @ P) * w + b   [16384 x 1024 x 1024]
    dim3 gb(DDIM / 128, BSZ / 128);  // (8, 128) = 1024 CTAs
    gemm_k<128, 128, 16, 8, 8, true><<<gb, 256>>>(eps, g0, nullptr, out, BSZ, DDIM, DDIM, w, b);
}

// round 17
// speedup vs baseline: 1.9287x; 1.9287x over previous
#include <cuda_runtime.h>
#include <cuda_bf16.h>
#include <cstdint>

#define DDIM 1024
#define BSZ  16384

// ---------------- device scratch (no allocations allowed) ----------------
__device__ float g_f0[DDIM * DDIM];
__device__ float g_f1[DDIM * DDIM];
__device__ float g_fA[DDIM * DDIM];
__device__ __nv_bfloat16 g_Ph[DDIM * DDIM], g_Pl[DDIM * DDIM];
__device__ __nv_bfloat16 g_Bh[DDIM * DDIM], g_Bl[DDIM * DDIM];
__device__ __nv_bfloat16 g_Eh[(size_t)BSZ * DDIM], g_El[(size_t)BSZ * DDIM];

// ---------------- warp-mma helpers (sm_80+ features only) ----------------
__device__ __forceinline__ uint32_t smem_u32(const void* p) {
    uint32_t a;
    asm("{ .reg .u64 t; cvta.to.shared.u64 t, %1; cvt.u32.u64 %0, t; }" : "=r"(a) : "l"(p));
    return a;
}
__device__ __forceinline__ void ldsm4(uint32_t r[4], uint32_t a) {
    asm volatile("ldmatrix.sync.aligned.m8n8.x4.shared.b16 {%0,%1,%2,%3}, [%4];"
                 : "=r"(r[0]), "=r"(r[1]), "=r"(r[2]), "=r"(r[3]) : "r"(a));
}
__device__ __forceinline__ void ldsm4t(uint32_t r[4], uint32_t a) {
    asm volatile("ldmatrix.sync.aligned.m8n8.x4.trans.shared.b16 {%0,%1,%2,%3}, [%4];"
                 : "=r"(r[0]), "=r"(r[1]), "=r"(r[2]), "=r"(r[3]) : "r"(a));
}
__device__ __forceinline__ void mma_bf16(float* c, const uint32_t a[4], uint32_t b0, uint32_t b1) {
    asm volatile(
        "mma.sync.aligned.m16n8k16.row.col.f32.bf16.bf16.f32 "
        "{%0,%1,%2,%3}, {%4,%5,%6,%7}, {%8,%9}, {%0,%1,%2,%3};"
        : "+f"(c[0]), "+f"(c[1]), "+f"(c[2]), "+f"(c[3])
        : "r"(a[0]), "r"(a[1]), "r"(a[2]), "r"(a[3]), "r"(b0), "r"(b1));
}

// ---------------- elementwise kernels ----------------
__global__ void init_P(const float* __restrict__ A, float* __restrict__ P) {
    int i = blockIdx.x * blockDim.x + threadIdx.x;
    int r = i >> 10, c = i & (DDIM - 1);
    P[i] = A[i] + (r == c ? 1.0f : 0.0f);
}

// fp32 -> (bf16 hi, bf16 lo) split, float4-vectorized.
__global__ void conv_split(const float* __restrict__ x, __nv_bfloat16* __restrict__ h,
                           __nv_bfloat16* __restrict__ l) {
    int i = blockIdx.x * blockDim.x + threadIdx.x;
    float4 v = ((const float4*)x)[i];
    __nv_bfloat16 h0 = __float2bfloat16(v.x), h1 = __float2bfloat16(v.y);
    __nv_bfloat16 h2 = __float2bfloat16(v.z), h3 = __float2bfloat16(v.w);
    __nv_bfloat162* H = (__nv_bfloat162*)h;
    __nv_bfloat162* L = (__nv_bfloat162*)l;
    H[2 * i]     = __nv_bfloat162{h0, h1};
    H[2 * i + 1] = __nv_bfloat162{h2, h3};
    L[2 * i]     = __nv_bfloat162{__float2bfloat16(v.x - __bfloat162float(h0)),
                                  __float2bfloat16(v.y - __bfloat162float(h1))};
    L[2 * i + 1] = __nv_bfloat162{__float2bfloat16(v.z - __bfloat162float(h2)),
                                  __float2bfloat16(v.w - __bfloat162float(h3))};
}

// ---------------- split-bf16 tensor-core GEMM (mma.sync) ----------------
// C[M,N] = (Ah+Al)[M,K] @ (Bh+Bl)[K,N]  (+Cs)  (then optional *w+bias).
// 256 thr = 8 warps (2 x 4). BM=128, BK=32. Warp tile 64 x (BN/4).
template <int BN, bool ADD, bool EPI>
__global__ void __launch_bounds__(256)
mgemm(const __nv_bfloat16* __restrict__ Ah, const __nv_bfloat16* __restrict__ Al,
      const __nv_bfloat16* __restrict__ Bh, const __nv_bfloat16* __restrict__ Bl,
      const float* __restrict__ Cs, float* __restrict__ C,
      int M, int N, int K,
      const float* __restrict__ w, const float* __restrict__ bias) {
    constexpr int BM = 128, BK = 32;
    constexpr int AP = BK + 8;          // A smem pitch (bf16): 40 -> 80B rows (16B mult.)
    constexpr int BP = BN + 8;          // B smem pitch: 136/72 -> 272B/144B rows
    constexpr int WN = BN / 4;          // warp n extent: 32 or 16
    constexpr int NT = WN / 8;          // 8-col n-tiles per warp: 4 or 2
    constexpr int NB = WN / 16;         // ldmatrix.x4 groups per warp: 2 or 1

    __shared__ __align__(16) __nv_bfloat16 sAh[BM * AP], sAl[BM * AP];
    __shared__ __align__(16) __nv_bfloat16 sBh[BK * BP], sBl[BK * BP];

    const int tid = threadIdx.x;
    const int wid = tid >> 5, lane = tid & 31;
    const int wm = wid >> 2, wn = wid & 3;
    const int m0 = blockIdx.x * BM, n0 = blockIdx.y * BN;

    float acc[4][NT][4];
#pragma unroll
    for (int i = 0; i < 4; i++)
#pragma unroll
        for (int j = 0; j < NT; j++)
#pragma unroll
            for (int k = 0; k < 4; k++) acc[i][j][k] = 0.0f;

    const int lrow = lane & 15, lseg = lane >> 4;         // A ldmatrix addressing
    const int bg = lane >> 3, br = lane & 7;              // B ldmatrix addressing

    for (int k0 = 0; k0 < K; k0 += BK) {
        // A tiles: BM x BK, row-major, 2 x uint4 per thread (per array)
#pragma unroll
        for (int i = 0; i < (BM * BK / 8) / 256; i++) {
            int idx = i * 256 + tid;
            int r = idx >> 2, c = (idx & 3) * 8;
            size_t g = (size_t)(m0 + r) * K + k0 + c;
            *(uint4*)&sAh[r * AP + c] = *(const uint4*)(Ah + g);
            *(uint4*)&sAl[r * AP + c] = *(const uint4*)(Al + g);
        }
        // B tiles: BK x BN, row-major
#pragma unroll
        for (int i = 0; i < (BK * BN / 8) / 256; i++) {
            int idx = i * 256 + tid;
            int r = idx / (BN / 8), c = (idx % (BN / 8)) * 8;
            size_t g = (size_t)(k0 + r) * N + n0 + c;
            *(uint4*)&sBh[r * BP + c] = *(const uint4*)(Bh + g);
            *(uint4*)&sBl[r * BP + c] = *(const uint4*)(Bl + g);
        }
        __syncthreads();

#pragma unroll
        for (int kk = 0; kk < BK / 16; kk++) {
            uint32_t ah[4][4], al[4][4], bh[NB][4], bl[NB][4];
#pragma unroll
            for (int mt = 0; mt < 4; mt++) {
                int off = (wm * 64 + mt * 16 + lrow) * AP + kk * 16 + lseg * 8;
                ldsm4(ah[mt], smem_u32(&sAh[off]));
                ldsm4(al[mt], smem_u32(&sAl[off]));
            }
#pragma unroll
            for (int nb = 0; nb < NB; nb++) {
                int off = (kk * 16 + (bg & 1) * 8 + br) * BP + wn * WN + nb * 16 + (bg >> 1) * 8;
                ldsm4t(bh[nb], smem_u32(&sBh[off]));
                ldsm4t(bl[nb], smem_u32(&sBl[off]));
            }
#pragma unroll
            for (int mt = 0; mt < 4; mt++)
#pragma unroll
                for (int nt = 0; nt < NT; nt++) {
                    int nb = nt >> 1, p = (nt & 1) * 2;
                    mma_bf16(acc[mt][nt], ah[mt], bh[nb][p], bh[nb][p + 1]);
                    mma_bf16(acc[mt][nt], ah[mt], bl[nb][p], bl[nb][p + 1]);
                    mma_bf16(acc[mt][nt], al[mt], bh[nb][p], bh[nb][p + 1]);
                }
        }
        __syncthreads();
    }

    // epilogue: fragment -> global, fused +Cs and *w+b
    const int qr = lane >> 2, qc = (lane & 3) * 2;
#pragma unroll
    for (int mt = 0; mt < 4; mt++)
#pragma unroll
        for (int nt = 0; nt < NT; nt++) {
            int row = m0 + wm * 64 + mt * 16 + qr;
            int col = n0 + wn * WN + nt * 8 + qc;
            float wv0 = 1.0f, wv1 = 1.0f, bv0 = 0.0f, bv1 = 0.0f;
            if (EPI) { wv0 = w[col]; wv1 = w[col + 1]; bv0 = bias[col]; bv1 = bias[col + 1]; }
#pragma unroll
            for (int h = 0; h < 2; h++) {
                size_t off = (size_t)(row + h * 8) * N + col;
                float v0 = acc[mt][nt][2 * h], v1 = acc[mt][nt][2 * h + 1];
                if (ADD) { float2 cs = *(const float2*)(Cs + off); v0 += cs.x; v1 += cs.y; }
                if (EPI) { v0 = fmaf(v0, wv0, bv0); v1 = fmaf(v1, wv1, bv1); }
                *(float2*)(C + off) = float2{v0, v1};
            }
        }
}

// ---------------- host ----------------
extern "C" void kernel_launch(void* const* d_in, const int* in_sizes, int n_in,
                              void* d_out, int out_size) {
    const float* eps = (const float*)d_in[0];
    const float* A   = (const float*)d_in[1];
    const float* w   = (const float*)d_in[2];
    const float* b   = (const float*)d_in[3];
    float* out = (float*)d_out;

    float *f0, *f1, *fA;
    __nv_bfloat16 *Ph, *Pl, *Bh, *Bl, *Eh, *El;
    cudaGetSymbolAddress((void**)&f0, g_f0);
    cudaGetSymbolAddress((void**)&f1, g_f1);
    cudaGetSymbolAddress((void**)&fA, g_fA);
    cudaGetSymbolAddress((void**)&Ph, g_Ph);
    cudaGetSymbolAddress((void**)&Pl, g_Pl);
    cudaGetSymbolAddress((void**)&Bh, g_Bh);
    cudaGetSymbolAddress((void**)&Bl, g_Bl);
    cudaGetSymbolAddress((void**)&Eh, g_Eh);
    cudaGetSymbolAddress((void**)&El, g_El);

    const int NELT = DDIM * DDIM;
    // P = I + A (fp32); split A, P, eps to bf16 hi/lo.
    init_P<<<NELT / 256, 256>>>(A, f0);
    conv_split<<<NELT / 1024, 256>>>(A, Bh, Bl);
    conv_split<<<NELT / 1024, 256>>>(f0, Ph, Pl);
    conv_split<<<(BSZ * DDIM) / 1024, 256>>>(eps, Eh, El);

    dim3 gs(DDIM / 128, DDIM / 64);     // (8, 16) = 128 CTAs, BN=64
    // (I-A)^{-1} ~= (I+A)(I+A^2)(I+A^4)(I+A^8)(I+A^16)   [Neumann deg 31]
    // j0: A2 = B@B ; P' = P + P@A2
    mgemm<64, false, false><<<gs, 256>>>(Bh, Bl, Bh, Bl, nullptr, fA, DDIM, DDIM, DDIM, nullptr, nullptr);
    conv_split<<<NELT / 1024, 256>>>(fA, Bh, Bl);
    mgemm<64, true,  false><<<gs, 256>>>(Ph, Pl, Bh, Bl, f0, f1, DDIM, DDIM, DDIM, nullptr, nullptr);
    conv_split<<<NELT / 1024, 256>>>(f1, Ph, Pl);
    // j1: A4 ; P''
    mgemm<64, false, false><<<gs, 256>>>(Bh, Bl, Bh, Bl, nullptr, fA, DDIM, DDIM, DDIM, nullptr, nullptr);
    conv_split<<<NELT / 1024, 256>>>(fA, Bh, Bl);
    mgemm<64, true,  false><<<gs, 256>>>(Ph, Pl, Bh, Bl, f1, f0, DDIM, DDIM, DDIM, nullptr, nullptr);
    conv_split<<<NELT / 1024, 256>>>(f0, Ph, Pl);
    // j2: A8 ; P'''
    mgemm<64, false, false><<<gs, 256>>>(Bh, Bl, Bh, Bl, nullptr, fA, DDIM, DDIM, DDIM, nullptr, nullptr);
    conv_split<<<NELT / 1024, 256>>>(fA, Bh, Bl);
    mgemm<64, true,  false><<<gs, 256>>>(Ph, Pl, Bh, Bl, f0, f1, DDIM, DDIM, DDIM, nullptr, nullptr);
    conv_split<<<NELT / 1024, 256>>>(f1, Ph, Pl);
    // j3: A16 ; final P
    mgemm<64, false, false><<<gs, 256>>>(Bh, Bl, Bh, Bl, nullptr, fA, DDIM, DDIM, DDIM, nullptr, nullptr);
    conv_split<<<NELT / 1024, 256>>>(fA, Bh, Bl);
    mgemm<64, true,  false><<<gs, 256>>>(Ph, Pl, Bh, Bl, f1, f0, DDIM, DDIM, DDIM, nullptr, nullptr);
    conv_split<<<NELT / 1024, 256>>>(f0, Ph, Pl);

    // out = (eps @ P) * w + b   [16384 x 1024 x 1024]
    dim3 gb(BSZ / 128, DDIM / 128);     // (128, 8) = 1024 CTAs, BN=128
    mgemm<128, false, true><<<gb, 256>>>(Eh, El, Ph, Pl, nullptr, out, BSZ, DDIM, DDIM, w, b);
}